// round 17
// baseline (speedup 1.0000x reference)
#include <cuda_runtime.h>
#include <cstdint>

// GroupedEmbeddingBag via uniform row-range decomposition.
// values: [T, L] int32, offsets: [T, B+1] int32, weights: [T, V, D] fp32,
// out: [B, T*D] fp32.
// Each warp owns a fixed 128-row contiguous range of one table's id stream
// (perfect load balance). Bag boundaries resolved during consumption:
// interior segments -> plain float4 store; range-boundary segments ->
// atomicAdd onto a base zeroed by the prep kernel. Prep (1 warp/range):
// binary-search the start bag, zero exactly the bags that receive atomics
// ({start_bag}) plus empty bags sitting exactly on the range boundary
// (which the main walk skips). No full-output zero pass.

static constexpr int T = 8;
static constexpr int V = 100000;
static constexpr int D = 128;
static constexpr int B = 4096;
static constexpr int RANGE = 128;               // rows per warp
static constexpr int MAX_RANGES = 16384;        // capacity (actual: 12800)

__device__ int g_start_bag[MAX_RANGES];

// ---------------- prep: start bag per range + targeted zeroing ----------------
__global__ void prep_kernel(const int* __restrict__ offsets,
                            float* __restrict__ out,
                            int ranges_per_table, int n_ranges)
{
    const int w    = blockIdx.x * (blockDim.x >> 5) + (threadIdx.x >> 5);
    const int lane = threadIdx.x & 31;
    if (w >= n_ranges) return;

    const int t  = w / ranges_per_table;
    const int r0 = (w - t * ranges_per_table) * RANGE;
    const int* offs = offsets + t * (B + 1);

    // first bag whose end > r0 (uniform across lanes)
    int lo = 0, hi = B;
    while (lo < hi) {
        const int mid = (lo + hi) >> 1;
        if (offs[mid + 1] <= r0) lo = mid + 1; else hi = mid;
    }
    if (lane == 0) g_start_bag[w] = lo;

    // Backward scan: empty bags exactly at r0 (start==end==r0) are skipped
    // by the main walk and must be zeroed here. Bag x-1 spans
    // [offs[x-1], offs[x]).
    int x = lo;
    while (x > 0 && offs[x] == r0 && offs[x - 1] == r0) x--;

    // Zero out[bb, t*D ..] for bb in [x, lo]: 32 lanes x float4 = 512 B each.
    const float4 z = make_float4(0.f, 0.f, 0.f, 0.f);
    for (int bb = x; bb <= lo; bb++) {
        float4* dst = reinterpret_cast<float4*>(out + (long long)bb * (T * D) + t * D);
        dst[lane] = z;
    }
}

// ---------------- main kernel (unchanged from R15) ----------------
__device__ __forceinline__ float4 ldg_na(const void* p) {
    float4 v;
    asm volatile("ld.global.nc.L1::no_allocate.v4.f32 {%0,%1,%2,%3}, [%4];"
                 : "=f"(v.x), "=f"(v.y), "=f"(v.z), "=f"(v.w)
                 : "l"(p));
    return v;
}

__global__ void __launch_bounds__(32)
grouped_embedding_bag_kernel(const int* __restrict__ values,
                             const int* __restrict__ offsets,
                             const float* __restrict__ weights,
                             float* __restrict__ out,
                             int L, int ranges_per_table)
{
    __shared__ int sidx[RANGE];

    const int w    = blockIdx.x;
    const int lane = threadIdx.x;

    const int t  = w / ranges_per_table;
    const int r0 = (w - t * ranges_per_table) * RANGE;
    const int r1 = r0 + RANGE;

    const int* offs = offsets + t * (B + 1);
    const int* vals = values + t * L + r0;

    // Stage this range's 128 indices in smem (4 coalesced loads).
    #pragma unroll
    for (int q = 0; q < 4; q++) sidx[lane + 32 * q] = vals[lane + 32 * q];
    __syncwarp();

    const char* __restrict__ Wb =
        reinterpret_cast<const char*>(weights + (long long)t * V * D);
    const unsigned lane_off = (unsigned)lane * 16u;

    int  b_cur = g_start_bag[w];
    int  e_cur = offs[b_cur + 1];       // > r0 by construction
    bool first_seg = true;

    float4 accA = make_float4(0.f, 0.f, 0.f, 0.f);
    float4 accB = make_float4(0.f, 0.f, 0.f, 0.f);

    auto flush = [&](bool atomic_) {
        float* dst = out + (long long)b_cur * (T * D) + t * D + lane * 4;
        const float vx = accA.x + accB.x, vy = accA.y + accB.y;
        const float vz = accA.z + accB.z, vw = accA.w + accB.w;
        if (atomic_) {
            atomicAdd(dst + 0, vx); atomicAdd(dst + 1, vy);
            atomicAdd(dst + 2, vz); atomicAdd(dst + 3, vw);
        } else {
            *reinterpret_cast<float4*>(dst) = make_float4(vx, vy, vz, vw);
        }
        accA = make_float4(0.f, 0.f, 0.f, 0.f);
        accB = make_float4(0.f, 0.f, 0.f, 0.f);
    };

    auto gather4 = [&](float4* buf, int j) {
        #pragma unroll
        for (int k = 0; k < 4; k++) {
            const unsigned idx = (unsigned)sidx[j + k];
            buf[k] = ldg_na(Wb + idx * 512u + lane_off);
        }
    };
    auto consume4 = [&](const float4* buf, int j) {
        #pragma unroll
        for (int k = 0; k < 4; k++) {
            const int r = r0 + j + k;
            if (r >= e_cur) {                       // bag ended inside range
                do {
                    flush(first_seg);               // in-loop flush never last
                    first_seg = false;
                    b_cur++;
                    e_cur = offs[b_cur + 1];
                } while (r >= e_cur);
            }
            if (k & 1) {
                accB.x += buf[k].x; accB.y += buf[k].y;
                accB.z += buf[k].z; accB.w += buf[k].w;
            } else {
                accA.x += buf[k].x; accA.y += buf[k].y;
                accA.z += buf[k].z; accA.w += buf[k].w;
            }
        }
    };

    // Double-buffered pipeline over 32 batches of 4 rows (RANGE=128 exact).
    float4 bufA[4], bufB[4];
    gather4(bufA, 0);
    for (int j = 0; j < RANGE; j += 8) {
        if (j + 4 < RANGE) gather4(bufB, j + 4);
        consume4(bufA, j);
        if (j + 8 < RANGE) gather4(bufA, j + 8);
        consume4(bufB, j + 4);
    }

    // Final segment: boundary iff first (left-cut) or bag extends past r1.
    flush(first_seg || e_cur > r1);
}

extern "C" void kernel_launch(void* const* d_in, const int* in_sizes, int n_in,
                              void* d_out, int out_size)
{
    const int*   values  = (const int*)d_in[0];    // [T, L] int32
    const int*   offsets = (const int*)d_in[1];    // [T, B+1] int32
    const float* weights = (const float*)d_in[2];  // [T, V, D] fp32
    float* out = (float*)d_out;                    // [B, T*D] fp32

    const int L = in_sizes[0] / T;
    const int ranges_per_table = L / RANGE;        // 1600 (L divisible by 128)
    const int n_ranges = T * ranges_per_table;     // 12800

    // 1) prep: start bags + targeted zeroing (1 warp per range)
    prep_kernel<<<(n_ranges + 3) / 4, 128>>>(offsets, out,
                                             ranges_per_table, n_ranges);

    // 2) main gather/pool
    grouped_embedding_bag_kernel<<<n_ranges, 32>>>(values, offsets, weights,
                                                   out, L, ranges_per_table);
}